// round 1
// baseline (speedup 1.0000x reference)
#include <cuda_runtime.h>
#include <cuda_bf16.h>
#include <math.h>

#define N_NODES 50000
#define N_EDGES 800000
#define EP      (N_EDGES + N_NODES)   // with self loops = 850000
#define GGR     512
#define HID     64

// ---------------- scratch (device globals; no allocs allowed) ----------------
__device__ float    g_z[N_NODES * 256];
__device__ float    g_h[N_NODES * 256];
__device__ float    g_as[N_NODES * 4];
__device__ float    g_ad[N_NODES * 4];
__device__ int      g_rowptr[N_NODES + 1];
__device__ int      g_cursor[N_NODES];
__device__ int      g_cnt[N_NODES];
__device__ int      g_srcs[EP];
__device__ unsigned g_pool[GGR * HID];

// ---------------- CSR build ----------------
__global__ void k_zero_cnt(int* cnt) {
    int i = blockIdx.x * blockDim.x + threadIdx.x;
    if (i < N_NODES) cnt[i] = 0;
}

__global__ void k_hist(const int* __restrict__ ei, int* cnt) {
    int i = blockIdx.x * blockDim.x + threadIdx.x;
    if (i >= EP) return;
    int d = (i < N_EDGES) ? ei[N_EDGES + i] : (i - N_EDGES);
    atomicAdd(&cnt[d], 1);
}

__global__ void k_scan(const int* __restrict__ cnt, int* rowptr, int* cursor) {
    __shared__ int sm[1024];
    __shared__ int carry_s;
    const int n = N_NODES;
    if (threadIdx.x == 0) carry_s = 0;
    __syncthreads();
    for (int base = 0; base < n; base += 1024) {
        int i = base + threadIdx.x;
        int v = (i < n) ? cnt[i] : 0;
        sm[threadIdx.x] = v;
        __syncthreads();
        for (int off = 1; off < 1024; off <<= 1) {
            int t = (threadIdx.x >= off) ? sm[threadIdx.x - off] : 0;
            __syncthreads();
            sm[threadIdx.x] += t;
            __syncthreads();
        }
        int carry = carry_s;
        int incl  = sm[threadIdx.x];
        int excl  = incl - v + carry;
        if (i < n) { rowptr[i] = excl; cursor[i] = excl; }
        if (i == n - 1) rowptr[n] = excl + v;
        __syncthreads();
        if (threadIdx.x == 1023) carry_s = carry + sm[1023];
        __syncthreads();
    }
}

__global__ void k_scatter(const int* __restrict__ ei, int* cursor, int* srcs) {
    int i = blockIdx.x * blockDim.x + threadIdx.x;
    if (i >= EP) return;
    int s, d;
    if (i < N_EDGES) { s = ei[i]; d = ei[N_EDGES + i]; }
    else             { s = d = i - N_EDGES; }
    int p = atomicAdd(&cursor[d], 1);
    srcs[p] = s;
}

// ---------------- GEMM:  C[M,NC] = A[M,K] @ B[K,NC]  (fp32) ----------------
// BM=128, BN=64, BK=32, 256 threads, 8x4 micro-tile.
template <int K, int NC>
__global__ void k_gemm(const float* __restrict__ A, const float* __restrict__ B,
                       float* __restrict__ Cm, int M) {
    const int BM = 128, BN = 64, BK = 32;
    __shared__ float As[BK][BM + 1];
    __shared__ float Bs[BK][BN];
    int tid = threadIdx.x;
    int tx = tid & 15;        // 0..15 -> 4 cols each
    int ty = tid >> 4;        // 0..15 -> 8 rows each
    int rowBase = blockIdx.x * BM;
    int colBase = blockIdx.y * BN;
    float acc[8][4];
#pragma unroll
    for (int i = 0; i < 8; i++)
#pragma unroll
        for (int j = 0; j < 4; j++) acc[i][j] = 0.f;

    for (int k0 = 0; k0 < K; k0 += BK) {
        // A tile: 128 rows x 32 k  = 1024 float4
#pragma unroll
        for (int i = 0; i < 4; i++) {
            int f  = tid + i * 256;
            int r  = f >> 3;            // row in tile
            int kq = f & 7;             // float4 idx along k
            int grow = rowBase + r;
            float4 v = make_float4(0.f, 0.f, 0.f, 0.f);
            if (grow < M)
                v = reinterpret_cast<const float4*>(A + (size_t)grow * K + k0)[kq];
            As[kq * 4 + 0][r] = v.x;
            As[kq * 4 + 1][r] = v.y;
            As[kq * 4 + 2][r] = v.z;
            As[kq * 4 + 3][r] = v.w;
        }
        // B tile: 32 rows x 64 cols = 512 float4
#pragma unroll
        for (int i = 0; i < 2; i++) {
            int f  = tid + i * 256;
            int r  = f >> 4;            // k row 0..31
            int cq = f & 15;            // float4 idx along cols
            float4 v = reinterpret_cast<const float4*>(B + (size_t)(k0 + r) * NC + colBase)[cq];
            reinterpret_cast<float4*>(&Bs[r][0])[cq] = v;
        }
        __syncthreads();
#pragma unroll
        for (int kk = 0; kk < BK; kk++) {
            float ra[8], rb[4];
#pragma unroll
            for (int i = 0; i < 8; i++) ra[i] = As[kk][ty * 8 + i];
#pragma unroll
            for (int j = 0; j < 4; j++) rb[j] = Bs[kk][tx * 4 + j];
#pragma unroll
            for (int i = 0; i < 8; i++)
#pragma unroll
                for (int j = 0; j < 4; j++) acc[i][j] = fmaf(ra[i], rb[j], acc[i][j]);
        }
        __syncthreads();
    }
#pragma unroll
    for (int i = 0; i < 8; i++) {
        int grow = rowBase + ty * 8 + i;
        if (grow < M) {
            float4 v = make_float4(acc[i][0], acc[i][1], acc[i][2], acc[i][3]);
            reinterpret_cast<float4*>(Cm + (size_t)grow * NC + colBase)[tx] = v;
        }
    }
}

// ---------------- attention coefficients a_s, a_d ----------------
// one warp per node; C must be 64.
template <int H>
__global__ void k_att(const float* __restrict__ z, const float* __restrict__ att_src,
                      const float* __restrict__ att_dst,
                      float* __restrict__ as_, float* __restrict__ ad_) {
    int gw   = (blockIdx.x * blockDim.x + threadIdx.x) >> 5;
    int lane = threadIdx.x & 31;
    if (gw >= N_NODES) return;
    const float* zr = z + (size_t)gw * (H * 64);
#pragma unroll
    for (int h = 0; h < H; h++) {
        float v1 = zr[h * 64 + lane];
        float v2 = zr[h * 64 + lane + 32];
        float ss = v1 * att_src[h * 64 + lane] + v2 * att_src[h * 64 + lane + 32];
        float dd = v1 * att_dst[h * 64 + lane] + v2 * att_dst[h * 64 + lane + 32];
#pragma unroll
        for (int off = 16; off; off >>= 1) {
            ss += __shfl_down_sync(0xffffffffu, ss, off);
            dd += __shfl_down_sync(0xffffffffu, dd, off);
        }
        if (lane == 0) { as_[gw * H + h] = ss; ad_[gw * H + h] = dd; }
    }
}

// ---------------- per-dst softmax + aggregation (+bias, +opt ELU) ----------------
// block = H*C threads, one block per dst node. CSR gives incoming edges.
template <int H, int C, bool ELU>
__global__ void k_agg(const float* __restrict__ z, const int* __restrict__ srcs,
                      const int* __restrict__ rowptr, const float* __restrict__ as_,
                      const float* __restrict__ ad_, const float* __restrict__ bias,
                      float* __restrict__ out) {
    constexpr int T = H * C;
    int n = blockIdx.x;
    int t = threadIdx.x;
    int h = t / C;
    int start = rowptr[n], end = rowptr[n + 1];
    int deg = end - start;

    __shared__ float sm_m[H];
    __shared__ float sm_s[H];
    __shared__ int   s_src[C];
    __shared__ float s_alpha[C * H];

    int warp = t >> 5, lane = t & 31;
    // phase 1: online softmax stats per head (warp per head)
    if (warp < H) {
        float adv = ad_[n * H + warp];
        float m = -1e30f, s = 0.f;
        for (int j = lane; j < deg; j += 32) {
            int sidx = srcs[start + j];
            float e = as_[sidx * H + warp] + adv;
            e = (e > 0.f) ? e : 0.2f * e;
            float nm = fmaxf(m, e);
            s = s * __expf(m - nm) + __expf(e - nm);
            m = nm;
        }
#pragma unroll
        for (int off = 16; off; off >>= 1) {
            float mo = __shfl_down_sync(0xffffffffu, m, off);
            float so = __shfl_down_sync(0xffffffffu, s, off);
            float nm = fmaxf(m, mo);
            s = s * __expf(m - nm) + so * __expf(mo - nm);
            m = nm;
        }
        if (lane == 0) { sm_m[warp] = m; sm_s[warp] = s; }
    }
    __syncthreads();

    // phase 2: chunked alpha + weighted accumulation
    float acc = 0.f;
    for (int base = 0; base < deg; base += C) {
        int len = min(C, deg - base);
        if (t < len) s_src[t] = srcs[start + base + t];
        __syncthreads();
        if (t < len * H) {
            int j  = t / H;
            int hh = t - j * H;
            int sidx = s_src[j];
            float e = as_[sidx * H + hh] + ad_[n * H + hh];
            e = (e > 0.f) ? e : 0.2f * e;
            s_alpha[j * H + hh] = __expf(e - sm_m[hh]) / (sm_s[hh] + 1e-16f);
        }
        __syncthreads();
        for (int j = 0; j < len; j++) {
            acc = fmaf(s_alpha[j * H + h], z[(size_t)s_src[j] * T + t], acc);
        }
        __syncthreads();
    }

    float v = acc + bias[t];
    if (ELU) v = (v > 0.f) ? v : expm1f(v);
    out[(size_t)n * T + t] = v;
}

// ---------------- global max pool ----------------
__device__ __forceinline__ unsigned f2ord(float f) {
    unsigned u = __float_as_uint(f);
    return (u & 0x80000000u) ? ~u : (u | 0x80000000u);
}
__device__ __forceinline__ float ord2f(unsigned u) {
    return __uint_as_float((u & 0x80000000u) ? (u ^ 0x80000000u) : ~u);
}

__global__ void k_pool_init(unsigned* pool) {
    int i = blockIdx.x * blockDim.x + threadIdx.x;
    if (i < GGR * HID) pool[i] = 0u;   // 0 < f2ord(any finite float >= -FLT_MAX)... and every graph non-empty
}

__global__ void k_pool_atomic(const float* __restrict__ hfin, const int* __restrict__ batch,
                              unsigned* pool) {
    int i = blockIdx.x * blockDim.x + threadIdx.x;
    if (i >= N_NODES * HID) return;
    int node = i >> 6, c = i & 63;
    atomicMax(&pool[batch[node] * HID + c], f2ord(hfin[i]));
}

__global__ void k_pool_write(const unsigned* __restrict__ pool, float* __restrict__ out) {
    int i = blockIdx.x * blockDim.x + threadIdx.x;
    if (i < GGR * HID) out[i] = ord2f(pool[i]);
}

// ---------------- launch ----------------
extern "C" void kernel_launch(void* const* d_in, const int* in_sizes, int n_in,
                              void* d_out, int out_size) {
    const float* x     = (const float*)d_in[0];
    const int*   ei    = (const int*)d_in[1];
    const int*   batch = (const int*)d_in[2];
    const float* W0    = (const float*)d_in[3];
    const float* AS0   = (const float*)d_in[4];
    const float* AD0   = (const float*)d_in[5];
    const float* B0    = (const float*)d_in[6];
    const float* W1    = (const float*)d_in[7];
    const float* AS1   = (const float*)d_in[8];
    const float* AD1   = (const float*)d_in[9];
    const float* B1    = (const float*)d_in[10];
    const float* W2    = (const float*)d_in[11];
    const float* AS2   = (const float*)d_in[12];
    const float* AD2   = (const float*)d_in[13];
    const float* B2    = (const float*)d_in[14];

    float *z, *h, *as_, *ad_;
    int *rowptr, *cursor, *cnt, *srcs;
    unsigned* pool;
    cudaGetSymbolAddress((void**)&z, g_z);
    cudaGetSymbolAddress((void**)&h, g_h);
    cudaGetSymbolAddress((void**)&as_, g_as);
    cudaGetSymbolAddress((void**)&ad_, g_ad);
    cudaGetSymbolAddress((void**)&rowptr, g_rowptr);
    cudaGetSymbolAddress((void**)&cursor, g_cursor);
    cudaGetSymbolAddress((void**)&cnt, g_cnt);
    cudaGetSymbolAddress((void**)&srcs, g_srcs);
    cudaGetSymbolAddress((void**)&pool, g_pool);

    const int M = N_NODES;

    // CSR build (counting sort by dst, self-loops appended)
    k_zero_cnt<<<(N_NODES + 255) / 256, 256>>>(cnt);
    k_hist<<<(EP + 255) / 256, 256>>>(ei, cnt);
    k_scan<<<1, 1024>>>(cnt, rowptr, cursor);
    k_scatter<<<(EP + 255) / 256, 256>>>(ei, cursor, srcs);

    dim3 g0((M + 127) / 128, 4);   // NC=256
    dim3 g2((M + 127) / 128, 1);   // NC=64
    int attGrid = (N_NODES * 32 + 255) / 256;

    // layer 0: x[.,64] @ W0[64,256]
    k_gemm<64, 256><<<g0, 256>>>(x, W0, z, M);
    k_att<4><<<attGrid, 256>>>(z, AS0, AD0, as_, ad_);
    k_agg<4, 64, true><<<M, 256>>>(z, srcs, rowptr, as_, ad_, B0, h);

    // layer 1: h[.,256] @ W1[256,256]
    k_gemm<256, 256><<<g0, 256>>>(h, W1, z, M);
    k_att<4><<<attGrid, 256>>>(z, AS1, AD1, as_, ad_);
    k_agg<4, 64, true><<<M, 256>>>(z, srcs, rowptr, as_, ad_, B1, h);

    // layer 2: h[.,256] @ W2[256,64], single head, no ELU, mean over 1 head = identity
    k_gemm<256, 64><<<g2, 256>>>(h, W2, z, M);
    k_att<1><<<attGrid, 256>>>(z, AS2, AD2, as_, ad_);
    k_agg<1, 64, false><<<M, 64>>>(z, srcs, rowptr, as_, ad_, B2, h);

    // pool
    k_pool_init<<<(GGR * HID + 255) / 256, 256>>>(pool);
    k_pool_atomic<<<(N_NODES * HID + 255) / 256, 256>>>(h, batch, pool);
    k_pool_write<<<(GGR * HID + 255) / 256, 256>>>(pool, (float*)d_out);
}

// round 3
// speedup vs baseline: 1.1011x; 1.1011x over previous
#include <cuda_runtime.h>
#include <cuda_bf16.h>
#include <math.h>
#include <stdint.h>

#define N_NODES 50000
#define N_EDGES 800000
#define EP      (N_EDGES + N_NODES)   // with self loops = 850000
#define GGR     512
#define HID     64

// ---------------- scratch (device globals; no allocs allowed) ----------------
__device__ float    g_z[N_NODES * 256];
__device__ float    g_h[N_NODES * 256];
__device__ __nv_bfloat16 g_Ahi[N_NODES * 256];
__device__ __nv_bfloat16 g_Alo[N_NODES * 256];
__device__ __nv_bfloat16 g_Bh[256 * 256];
__device__ __nv_bfloat16 g_Bl[256 * 256];
__device__ float    g_as[N_NODES * 4];
__device__ float    g_ad[N_NODES * 4];
__device__ int      g_rowptr[N_NODES + 1];
__device__ int      g_cursor[N_NODES];
__device__ int      g_cnt[N_NODES];
__device__ int      g_srcs[EP];
__device__ unsigned g_pool[GGR * HID];

// ---------------- CSR build ----------------
__global__ void k_zero_cnt(int* cnt) {
    int i = blockIdx.x * blockDim.x + threadIdx.x;
    if (i < N_NODES) cnt[i] = 0;
}

__global__ void k_hist(const int* __restrict__ ei, int* cnt) {
    int i = blockIdx.x * blockDim.x + threadIdx.x;
    if (i >= EP) return;
    int d = (i < N_EDGES) ? ei[N_EDGES + i] : (i - N_EDGES);
    atomicAdd(&cnt[d], 1);
}

__global__ void k_scan(const int* __restrict__ cnt, int* rowptr, int* cursor) {
    __shared__ int sm[1024];
    __shared__ int carry_s;
    const int n = N_NODES;
    if (threadIdx.x == 0) carry_s = 0;
    __syncthreads();
    for (int base = 0; base < n; base += 1024) {
        int i = base + threadIdx.x;
        int v = (i < n) ? cnt[i] : 0;
        sm[threadIdx.x] = v;
        __syncthreads();
        for (int off = 1; off < 1024; off <<= 1) {
            int t = (threadIdx.x >= off) ? sm[threadIdx.x - off] : 0;
            __syncthreads();
            sm[threadIdx.x] += t;
            __syncthreads();
        }
        int carry = carry_s;
        int incl  = sm[threadIdx.x];
        int excl  = incl - v + carry;
        if (i < n) { rowptr[i] = excl; cursor[i] = excl; }
        if (i == n - 1) rowptr[n] = excl + v;
        __syncthreads();
        if (threadIdx.x == 1023) carry_s = carry + sm[1023];
        __syncthreads();
    }
}

__global__ void k_scatter(const int* __restrict__ ei, int* cursor, int* srcs) {
    int i = blockIdx.x * blockDim.x + threadIdx.x;
    if (i >= EP) return;
    int s, d;
    if (i < N_EDGES) { s = ei[i]; d = ei[N_EDGES + i]; }
    else             { s = d = i - N_EDGES; }
    int p = atomicAdd(&cursor[d], 1);
    srcs[p] = s;
}

// ---------------- bf16 split helpers ----------------
__global__ void k_split(const float* __restrict__ a, __nv_bfloat16* __restrict__ hi,
                        __nv_bfloat16* __restrict__ lo, int n) {
    int i = blockIdx.x * blockDim.x + threadIdx.x;
    if (i >= n) return;
    float v = a[i];
    __nv_bfloat16 h = __float2bfloat16(v);
    hi[i] = h;
    lo[i] = __float2bfloat16(v - __bfloat162float(h));
}

// W[K,NC] row-major -> Bt[NC,K] hi/lo (col-major B for mma.sync)
__global__ void k_wsplit(const float* __restrict__ w, __nv_bfloat16* __restrict__ bh,
                         __nv_bfloat16* __restrict__ bl, int K, int NC) {
    int i = blockIdx.x * blockDim.x + threadIdx.x;
    if (i >= K * NC) return;
    int k = i / NC, n = i - k * NC;
    float v = w[i];
    __nv_bfloat16 h = __float2bfloat16(v);
    bh[n * K + k] = h;
    bl[n * K + k] = __float2bfloat16(v - __bfloat162float(h));
}

// ---------------- HMMA GEMM: C[M,NC] = A[M,K] @ B[K,NC] (bf16-split, fp32 acc)
// mma.sync.m16n8k16 row.col; A hi/lo [M,K] row-major, Bt hi/lo [NC,K] row-major.
// Block 128x64 (8 warps, warp tile 32x32). K chunked by 32.
__device__ __forceinline__ void mma_bf16(float* d, const uint32_t* a, const uint32_t* b) {
    asm volatile(
        "mma.sync.aligned.m16n8k16.row.col.f32.bf16.bf16.f32 "
        "{%0,%1,%2,%3}, {%4,%5,%6,%7}, {%8,%9}, {%0,%1,%2,%3};"
        : "+f"(d[0]), "+f"(d[1]), "+f"(d[2]), "+f"(d[3])
        : "r"(a[0]), "r"(a[1]), "r"(a[2]), "r"(a[3]), "r"(b[0]), "r"(b[1]));
}

template <int K, int NC>
__global__ void __launch_bounds__(256) k_gemm_mma(
    const __nv_bfloat16* __restrict__ Ahi, const __nv_bfloat16* __restrict__ Alo,
    const __nv_bfloat16* __restrict__ Bhi, const __nv_bfloat16* __restrict__ Blo,
    float* __restrict__ Cm, int M)
{
    constexpr int KC  = 32;     // k chunk
    constexpr int AST = 40;     // smem row stride in bf16 (conflict-free padding)
    __shared__ __nv_bfloat16 sAh[128 * AST];
    __shared__ __nv_bfloat16 sAl[128 * AST];
    __shared__ __nv_bfloat16 sBh[64 * AST];
    __shared__ __nv_bfloat16 sBl[64 * AST];

    const int tid  = threadIdx.x;
    const int lane = tid & 31;
    const int wid  = tid >> 5;
    const int wm   = wid & 3;          // 4 m-warps
    const int wn   = wid >> 2;         // 2 n-warps
    const int rowBase = blockIdx.x * 128;
    const int colBase = blockIdx.y * 64;
    const int g   = lane >> 2;
    const int tig = lane & 3;

    float d[2][4][4];
#pragma unroll
    for (int mi = 0; mi < 2; mi++)
#pragma unroll
        for (int ni = 0; ni < 4; ni++)
#pragma unroll
            for (int q = 0; q < 4; q++) d[mi][ni][q] = 0.f;

    for (int k0 = 0; k0 < K; k0 += KC) {
        // A chunk: 128 rows x 16 b32 (hi + lo)
#pragma unroll
        for (int i = tid; i < 128 * 16; i += 256) {
            int r = i >> 4, c = i & 15;
            int grow = rowBase + r;
            uint32_t vh = 0, vl = 0;
            if (grow < M) {
                size_t idx = ((size_t)grow * K + k0) >> 1;  // in b32 units
                vh = ((const uint32_t*)Ahi)[idx + c];
                vl = ((const uint32_t*)Alo)[idx + c];
            }
            *(uint32_t*)&sAh[r * AST + 2 * c] = vh;
            *(uint32_t*)&sAl[r * AST + 2 * c] = vl;
        }
        // B chunk: 64 rows (n) x 16 b32
#pragma unroll
        for (int i = tid; i < 64 * 16; i += 256) {
            int r = i >> 4, c = i & 15;
            size_t idx = ((size_t)(colBase + r) * K + k0) >> 1;
            *(uint32_t*)&sBh[r * AST + 2 * c] = ((const uint32_t*)Bhi)[idx + c];
            *(uint32_t*)&sBl[r * AST + 2 * c] = ((const uint32_t*)Blo)[idx + c];
        }
        __syncthreads();

#pragma unroll
        for (int ks = 0; ks < KC; ks += 16) {
            uint32_t ah[2][4], al[2][4], bh[4][2], bl[4][2];
#pragma unroll
            for (int mi = 0; mi < 2; mi++) {
                int r0 = (wm * 32 + mi * 16 + g) * AST + ks + 2 * tig;
                int r8 = r0 + 8 * AST;
                ah[mi][0] = *(const uint32_t*)&sAh[r0];
                ah[mi][1] = *(const uint32_t*)&sAh[r8];
                ah[mi][2] = *(const uint32_t*)&sAh[r0 + 8];
                ah[mi][3] = *(const uint32_t*)&sAh[r8 + 8];
                al[mi][0] = *(const uint32_t*)&sAl[r0];
                al[mi][1] = *(const uint32_t*)&sAl[r8];
                al[mi][2] = *(const uint32_t*)&sAl[r0 + 8];
                al[mi][3] = *(const uint32_t*)&sAl[r8 + 8];
            }
#pragma unroll
            for (int ni = 0; ni < 4; ni++) {
                int br = (wn * 32 + ni * 8 + g) * AST + ks + 2 * tig;
                bh[ni][0] = *(const uint32_t*)&sBh[br];
                bh[ni][1] = *(const uint32_t*)&sBh[br + 8];
                bl[ni][0] = *(const uint32_t*)&sBl[br];
                bl[ni][1] = *(const uint32_t*)&sBl[br + 8];
            }
#pragma unroll
            for (int mi = 0; mi < 2; mi++)
#pragma unroll
                for (int ni = 0; ni < 4; ni++) {
                    mma_bf16(d[mi][ni], ah[mi], bh[ni]);
                    mma_bf16(d[mi][ni], ah[mi], bl[ni]);
                    mma_bf16(d[mi][ni], al[mi], bh[ni]);
                }
        }
        __syncthreads();
    }

    // epilogue
#pragma unroll
    for (int mi = 0; mi < 2; mi++) {
        int row0 = rowBase + wm * 32 + mi * 16 + g;
        int row8 = row0 + 8;
#pragma unroll
        for (int ni = 0; ni < 4; ni++) {
            int col = colBase + wn * 32 + ni * 8 + 2 * tig;
            if (row0 < M) {
                float2* p = (float2*)(Cm + (size_t)row0 * NC + col);
                *p = make_float2(d[mi][ni][0], d[mi][ni][1]);
            }
            if (row8 < M) {
                float2* p = (float2*)(Cm + (size_t)row8 * NC + col);
                *p = make_float2(d[mi][ni][2], d[mi][ni][3]);
            }
        }
    }
}

// ---------------- attention coefficients a_s, a_d ----------------
template <int H>
__global__ void k_att(const float* __restrict__ z, const float* __restrict__ att_src,
                      const float* __restrict__ att_dst,
                      float* __restrict__ as_, float* __restrict__ ad_) {
    int gw   = (blockIdx.x * blockDim.x + threadIdx.x) >> 5;
    int lane = threadIdx.x & 31;
    if (gw >= N_NODES) return;
    const float* zr = z + (size_t)gw * (H * 64);
#pragma unroll
    for (int h = 0; h < H; h++) {
        float v1 = zr[h * 64 + lane];
        float v2 = zr[h * 64 + lane + 32];
        float ss = v1 * att_src[h * 64 + lane] + v2 * att_src[h * 64 + lane + 32];
        float dd = v1 * att_dst[h * 64 + lane] + v2 * att_dst[h * 64 + lane + 32];
#pragma unroll
        for (int off = 16; off; off >>= 1) {
            ss += __shfl_down_sync(0xffffffffu, ss, off);
            dd += __shfl_down_sync(0xffffffffu, dd, off);
        }
        if (lane == 0) { as_[gw * H + h] = ss; ad_[gw * H + h] = dd; }
    }
}

// ---------------- per-dst softmax + aggregation (+bias, +opt ELU, +opt split) --
template <int H, int C, bool ELU, bool SPLIT>
__global__ void k_agg(const float* __restrict__ z, const int* __restrict__ srcs,
                      const int* __restrict__ rowptr, const float* __restrict__ as_,
                      const float* __restrict__ ad_, const float* __restrict__ bias,
                      float* __restrict__ out,
                      __nv_bfloat16* __restrict__ ohi, __nv_bfloat16* __restrict__ olo) {
    constexpr int T = H * C;
    int n = blockIdx.x;
    int t = threadIdx.x;
    int h = t / C;
    int start = rowptr[n], end = rowptr[n + 1];
    int deg = end - start;

    __shared__ float sm_m[H];
    __shared__ float sm_s[H];
    __shared__ int   s_src[C];
    __shared__ float s_alpha[C * H];

    int warp = t >> 5, lane = t & 31;
    if (warp < H) {
        float adv = ad_[n * H + warp];
        float m = -1e30f, s = 0.f;
        for (int j = lane; j < deg; j += 32) {
            int sidx = srcs[start + j];
            float e = as_[sidx * H + warp] + adv;
            e = (e > 0.f) ? e : 0.2f * e;
            float nm = fmaxf(m, e);
            s = s * __expf(m - nm) + __expf(e - nm);
            m = nm;
        }
#pragma unroll
        for (int off = 16; off; off >>= 1) {
            float mo = __shfl_down_sync(0xffffffffu, m, off);
            float so = __shfl_down_sync(0xffffffffu, s, off);
            float nm = fmaxf(m, mo);
            s = s * __expf(m - nm) + so * __expf(mo - nm);
            m = nm;
        }
        if (lane == 0) { sm_m[warp] = m; sm_s[warp] = s; }
    }
    __syncthreads();

    float acc = 0.f;
    for (int base = 0; base < deg; base += C) {
        int len = min(C, deg - base);
        if (t < len) s_src[t] = srcs[start + base + t];
        __syncthreads();
        if (t < len * H) {
            int j  = t / H;
            int hh = t - j * H;
            int sidx = s_src[j];
            float e = as_[sidx * H + hh] + ad_[n * H + hh];
            e = (e > 0.f) ? e : 0.2f * e;
            s_alpha[j * H + hh] = __expf(e - sm_m[hh]) / (sm_s[hh] + 1e-16f);
        }
        __syncthreads();
        for (int j = 0; j < len; j++) {
            acc = fmaf(s_alpha[j * H + h], z[(size_t)s_src[j] * T + t], acc);
        }
        __syncthreads();
    }

    float v = acc + bias[t];
    if (ELU) v = (v > 0.f) ? v : expm1f(v);
    out[(size_t)n * T + t] = v;
    if (SPLIT) {
        __nv_bfloat16 hh = __float2bfloat16(v);
        ohi[(size_t)n * T + t] = hh;
        olo[(size_t)n * T + t] = __float2bfloat16(v - __bfloat162float(hh));
    }
}

// ---------------- global max pool ----------------
__device__ __forceinline__ unsigned f2ord(float f) {
    unsigned u = __float_as_uint(f);
    return (u & 0x80000000u) ? ~u : (u | 0x80000000u);
}
__device__ __forceinline__ float ord2f(unsigned u) {
    return __uint_as_float((u & 0x80000000u) ? (u ^ 0x80000000u) : ~u);
}

__global__ void k_pool_init(unsigned* pool) {
    int i = blockIdx.x * blockDim.x + threadIdx.x;
    if (i < GGR * HID) pool[i] = 0u;
}

__global__ void k_pool_atomic(const float* __restrict__ hfin, const int* __restrict__ batch,
                              unsigned* pool) {
    int i = blockIdx.x * blockDim.x + threadIdx.x;
    if (i >= N_NODES * HID) return;
    int node = i >> 6, c = i & 63;
    atomicMax(&pool[batch[node] * HID + c], f2ord(hfin[i]));
}

__global__ void k_pool_write(const unsigned* __restrict__ pool, float* __restrict__ out) {
    int i = blockIdx.x * blockDim.x + threadIdx.x;
    if (i < GGR * HID) out[i] = ord2f(pool[i]);
}

// ---------------- launch ----------------
extern "C" void kernel_launch(void* const* d_in, const int* in_sizes, int n_in,
                              void* d_out, int out_size) {
    const float* x     = (const float*)d_in[0];
    const int*   ei    = (const int*)d_in[1];
    const int*   batch = (const int*)d_in[2];
    const float* W0    = (const float*)d_in[3];
    const float* AS0   = (const float*)d_in[4];
    const float* AD0   = (const float*)d_in[5];
    const float* B0    = (const float*)d_in[6];
    const float* W1    = (const float*)d_in[7];
    const float* AS1   = (const float*)d_in[8];
    const float* AD1   = (const float*)d_in[9];
    const float* B1    = (const float*)d_in[10];
    const float* W2    = (const float*)d_in[11];
    const float* AS2   = (const float*)d_in[12];
    const float* AD2   = (const float*)d_in[13];
    const float* B2    = (const float*)d_in[14];

    float *z, *h, *as_, *ad_;
    __nv_bfloat16 *ahi, *alo, *bh, *bl;
    int *rowptr, *cursor, *cnt, *srcs;
    unsigned* pool;
    cudaGetSymbolAddress((void**)&z, g_z);
    cudaGetSymbolAddress((void**)&h, g_h);
    cudaGetSymbolAddress((void**)&ahi, g_Ahi);
    cudaGetSymbolAddress((void**)&alo, g_Alo);
    cudaGetSymbolAddress((void**)&bh, g_Bh);
    cudaGetSymbolAddress((void**)&bl, g_Bl);
    cudaGetSymbolAddress((void**)&as_, g_as);
    cudaGetSymbolAddress((void**)&ad_, g_ad);
    cudaGetSymbolAddress((void**)&rowptr, g_rowptr);
    cudaGetSymbolAddress((void**)&cursor, g_cursor);
    cudaGetSymbolAddress((void**)&cnt, g_cnt);
    cudaGetSymbolAddress((void**)&srcs, g_srcs);
    cudaGetSymbolAddress((void**)&pool, g_pool);

    const int M = N_NODES;
    const int GEMM_GRID = (M + 127) / 128;   // 391

    // CSR build (counting sort by dst, self-loops appended)
    k_zero_cnt<<<(N_NODES + 255) / 256, 256>>>(cnt);
    k_hist<<<(EP + 255) / 256, 256>>>(ei, cnt);
    k_scan<<<1, 1024>>>(cnt, rowptr, cursor);
    k_scatter<<<(EP + 255) / 256, 256>>>(ei, cursor, srcs);

    int attGrid = (N_NODES * 32 + 255) / 256;

    // ---- layer 0: x[.,64] @ W0[64,256]
    k_split<<<(N_NODES * 64 + 255) / 256, 256>>>(x, ahi, alo, N_NODES * 64);
    k_wsplit<<<(64 * 256 + 255) / 256, 256>>>(W0, bh, bl, 64, 256);
    k_gemm_mma<64, 256><<<dim3(GEMM_GRID, 4), 256>>>(ahi, alo, bh, bl, z, M);
    k_att<4><<<attGrid, 256>>>(z, AS0, AD0, as_, ad_);
    k_agg<4, 64, true, true><<<M, 256>>>(z, srcs, rowptr, as_, ad_, B0, h, ahi, alo);

    // ---- layer 1: h[.,256] @ W1[256,256]
    k_wsplit<<<(256 * 256 + 255) / 256, 256>>>(W1, bh, bl, 256, 256);
    k_gemm_mma<256, 256><<<dim3(GEMM_GRID, 4), 256>>>(ahi, alo, bh, bl, z, M);
    k_att<4><<<attGrid, 256>>>(z, AS1, AD1, as_, ad_);
    k_agg<4, 64, true, true><<<M, 256>>>(z, srcs, rowptr, as_, ad_, B1, h, ahi, alo);

    // ---- layer 2: h[.,256] @ W2[256,64], single head, mean over 1 head = identity
    k_wsplit<<<(256 * 64 + 255) / 256, 256>>>(W2, bh, bl, 256, 64);
    k_gemm_mma<256, 64><<<dim3(GEMM_GRID, 1), 256>>>(ahi, alo, bh, bl, z, M);
    k_att<1><<<attGrid, 256>>>(z, AS2, AD2, as_, ad_);
    k_agg<1, 64, false, false><<<M, 64>>>(z, srcs, rowptr, as_, ad_, B2, h, (__nv_bfloat16*)0, (__nv_bfloat16*)0);

    // ---- pool
    k_pool_init<<<(GGR * HID + 255) / 256, 256>>>(pool);
    k_pool_atomic<<<(N_NODES * HID + 255) / 256, 256>>>(h, batch, pool);
    k_pool_write<<<(GGR * HID + 255) / 256, 256>>>(pool, (float*)d_out);
}